// round 14
// baseline (speedup 1.0000x reference)
#include <cuda_runtime.h>
#include <cuda_bf16.h>
#include <math.h>
#include <stdint.h>

#define B_    32
#define T_    512
#define H_    256
#define C2H   512        // 2H
#define HP    4096       // H*P
#define M_    (B_*T_)    // 16384 rows
#define NITER 4
#define CAP   512        // max rescore candidates per phase
#define MARGIN 0.015f

// ---------------- static device buffers (no dynamic alloc) ----------------
__device__ __align__(128) __nv_bfloat16 g_Et[(size_t)M_*C2H];
__device__ __align__(128) float         g_Etf[(size_t)M_*C2H];
__device__ __align__(128) __nv_bfloat16 g_Y1s[(size_t)M_*HP];          // 128MB
__device__ __align__(128) __nv_bfloat16 g_Y1e[(size_t)M_*HP];          // 128MB
__device__ __align__(128) __nv_bfloat16 g_w1sb[HP*C2H];
__device__ __align__(128) __nv_bfloat16 g_w1eb[HP*C2H];
__device__ __align__(128) float         g_w1srT[H_*HP];
__device__ __align__(128) float         g_w1erT[H_*HP];
__device__ __align__(128) __nv_bfloat16 g_w2sb[HP*H_];
__device__ __align__(128) __nv_bfloat16 g_w2eb[HP*H_];
__device__ float         g_WDsT[5*H_*H_];
__device__ float         g_WDeT[5*H_*H_];
__device__ float         g_WihT[1024*1024];
__device__ float         g_WhhT[H_*1024];
__device__ float         g_WmlpT[H_*H_];
__device__ __align__(128) __nv_bfloat16 g_m1[M_*H_];
__device__ __align__(128) __nv_bfloat16 g_m2a[M_*H_];
__device__ float         g_scores[M_];
__device__ float         g_hx[B_*H_], g_cx[B_*H_];
__device__ float         g_encs[B_*C2H], g_ence[B_*C2H];
__device__ float         g_r[B_*H_];
__device__ __align__(16) float g_d[B_*HP];
// exact-rescore scratch
__device__ int           g_ncand8[8];
__device__ int           g_cands[CAP];
__device__ float         g_m1x[CAP*H_];
__device__ float         g_m2x[CAP*H_];
__device__ float         g_sexact[CAP];

// ---------------- helpers ----------------
__device__ __forceinline__ uint32_t smem_u32(const void* p) {
    uint32_t a;
    asm("{ .reg .u64 t; cvta.to.shared.u64 t, %1; cvt.u32.u64 %0, t; }" : "=r"(a) : "l"(p));
    return a;
}
__device__ __forceinline__ void cp16(uint32_t smem, const void* g) {
    asm volatile("cp.async.cg.shared.global [%0], [%1], 16;" :: "r"(smem), "l"(g) : "memory");
}
#define CP_COMMIT() asm volatile("cp.async.commit_group;" ::: "memory")
#define CP_WAIT1()  asm volatile("cp.async.wait_group 1;" ::: "memory")
__device__ __forceinline__ void ldsm4(uint32_t* r, uint32_t addr) {
    asm volatile("ldmatrix.sync.aligned.m8n8.x4.shared.b16 {%0,%1,%2,%3}, [%4];"
        : "=r"(r[0]), "=r"(r[1]), "=r"(r[2]), "=r"(r[3]) : "r"(addr));
}
__device__ __forceinline__ void mma16816(float* c, const uint32_t* a, const uint32_t* b) {
    asm volatile(
        "mma.sync.aligned.m16n8k16.row.col.f32.bf16.bf16.f32 "
        "{%0,%1,%2,%3}, {%4,%5,%6,%7}, {%8,%9}, {%0,%1,%2,%3};\n"
        : "+f"(c[0]), "+f"(c[1]), "+f"(c[2]), "+f"(c[3])
        : "r"(a[0]), "r"(a[1]), "r"(a[2]), "r"(a[3]), "r"(b[0]), "r"(b[1]));
}

// ---------------- prep kernels ----------------
__global__ void k_init(const float* __restrict__ enc) {
    int b = blockIdx.x, c = threadIdx.x;   // 512 threads
    float v = enc[(size_t)b*C2H*T_ + (size_t)c*T_ + 0];
    g_encs[b*C2H + c] = v;
    g_ence[b*C2H + c] = v;
    if (c < H_) { g_hx[b*H_ + c] = 0.f; g_cx[b*H_ + c] = 0.f; }
    if (b == 0 && c < 8) g_ncand8[c] = 0;
}

__global__ void k_tEt(const float* __restrict__ enc) {
    __shared__ float tile[32][33];
    int b = blockIdx.z;
    int t0 = blockIdx.x*32, c0 = blockIdx.y*32;
    for (int i = threadIdx.y; i < 32; i += 8)
        tile[i][threadIdx.x] = enc[(size_t)b*C2H*T_ + (size_t)(c0+i)*T_ + t0 + threadIdx.x];
    __syncthreads();
    for (int i = threadIdx.y; i < 32; i += 8) {
        float v = tile[threadIdx.x][i];
        size_t o = (size_t)b*T_*C2H + (size_t)(t0+i)*C2H + c0 + threadIdx.x;
        g_Et[o]  = __float2bfloat16_rn(v);
        g_Etf[o] = v;
    }
}

__global__ void k_w1prep(const float* __restrict__ w1, int useEnd) {
    __nv_bfloat16* wb = useEnd ? g_w1eb : g_w1sb;
    float* wrT = useEnd ? g_w1erT : g_w1srT;
    int total0 = HP*C2H;
    for (int idx = blockIdx.x*blockDim.x + threadIdx.x; idx < total0; idx += gridDim.x*blockDim.x) {
        int j = idx / C2H, k = idx % C2H;
        wb[idx] = __float2bfloat16_rn(w1[(size_t)j*768 + k]);
    }
    int total1 = H_*HP;
    for (int idx = blockIdx.x*blockDim.x + threadIdx.x; idx < total1; idx += gridDim.x*blockDim.x) {
        int k = idx / HP, j = idx % HP;
        wrT[idx] = w1[(size_t)j*768 + 512 + k];
    }
}

__global__ void k_w2prep(const float* __restrict__ w2, int useEnd) {
    __nv_bfloat16* out = useEnd ? g_w2eb : g_w2sb;
    int total = HP*H_;
    for (int idx = blockIdx.x*blockDim.x + threadIdx.x; idx < total; idx += gridDim.x*blockDim.x)
        out[idx] = __float2bfloat16_rn(w2[idx]);
}

__global__ void k_WDprep(const float* __restrict__ WD, int useEnd) {
    float* out = useEnd ? g_WDeT : g_WDsT;
    int total = 5*H_*H_;
    for (int idx = blockIdx.x*blockDim.x + threadIdx.x; idx < total; idx += gridDim.x*blockDim.x) {
        int k = idx / H_, h = idx % H_;
        out[idx] = WD[(size_t)h*(5*H_) + k];
    }
}

__global__ void k_lstmprep(const float* __restrict__ Wih, const float* __restrict__ Whh,
                           const float* __restrict__ Wmlp) {
    int stride = gridDim.x*blockDim.x;
    for (int idx = blockIdx.x*blockDim.x + threadIdx.x; idx < 1024*1024; idx += stride) {
        int k = idx / 1024, j = idx % 1024;
        g_WihT[idx] = Wih[(size_t)j*1024 + k];
    }
    for (int idx = blockIdx.x*blockDim.x + threadIdx.x; idx < H_*1024; idx += stride) {
        int k = idx / 1024, j = idx % 1024;
        g_WhhT[idx] = Whh[(size_t)j*H_ + k];
    }
    for (int idx = blockIdx.x*blockDim.x + threadIdx.x; idx < H_*H_; idx += stride) {
        int k = idx / H_, j = idx % H_;
        g_WmlpT[idx] = Wmlp[(size_t)j*H_ + k];
    }
}

// ---------------- pipelined mma.sync GEMM (3-stage) ----------------
#define ROWB    144
#define STAGE_A (128*ROWB)
#define STAGE_BYTES (2*STAGE_A)
#define GEMM_DSMEM (3*STAGE_BYTES)

template<int MODE>
__global__ __launch_bounds__(256, 2)
void gemm_cp(const float* __restrict__ bias, int useEnd) {
    constexpr int K  = (MODE == 0) ? 512 : 256;
    constexpr int NK = K / 64;
    const __nv_bfloat16* A  = (MODE == 0) ? g_Et : g_m1;
    const __nv_bfloat16* Bm = (MODE == 0) ? (useEnd ? g_w1eb : g_w1sb)
                                          : (useEnd ? g_w2eb : g_w2sb);
    __nv_bfloat16* C        = (MODE == 0) ? (useEnd ? g_Y1e : g_Y1s) : g_m2a;

    extern __shared__ __align__(16) char dynsm[];
    uint32_t smbase = smem_u32(dynsm);
    __shared__ float sbias[128];

    int tid = threadIdx.x, wid = tid >> 5, lane = tid & 31;
    int m0 = blockIdx.y*128, n0 = blockIdx.x*128;
    int wm = wid >> 2, wn = wid & 3;
    int g = lane >> 2, tig = lane & 3;
    int l7 = lane & 7, sel = lane >> 3;

    if (tid < 128) sbias[tid] = bias[n0 + tid];

    float acc[4][4][4];
    #pragma unroll
    for (int a = 0; a < 4; a++)
        #pragma unroll
        for (int bq = 0; bq < 4; bq++)
            #pragma unroll
            for (int cq = 0; cq < 4; cq++) acc[a][bq][cq] = 0.f;

    auto load_stage = [&](int kt, int buf) {
        uint32_t sb = smbase + buf*STAGE_BYTES;
        #pragma unroll
        for (int i = 0; i < 8; i++) {
            int q = tid + (i & 3)*256;
            int r_ = q >> 3, c = q & 7;
            if (i < 4)
                cp16(sb + r_*ROWB + c*16, &A[(size_t)(m0+r_)*K + kt*64 + c*8]);
            else
                cp16(sb + STAGE_A + r_*ROWB + c*16, &Bm[(size_t)(n0+r_)*K + kt*64 + c*8]);
        }
    };

    load_stage(0, 0); CP_COMMIT();
    load_stage(1, 1); CP_COMMIT();
    CP_WAIT1();
    __syncthreads();

    uint32_t aRowOff = (uint32_t)(wm*64 + l7 + (sel & 1)*8) * ROWB + (uint32_t)(sel >> 1)*16;
    uint32_t bRowOff0 = (uint32_t)(wn*32 + l7 + (sel >> 1)*8) * ROWB + (uint32_t)(sel & 1)*16;

    for (int kt = 0; kt < NK; kt++) {
        uint32_t aB = smbase + (kt % 3)*STAGE_BYTES;
        uint32_t bB = aB + STAGE_A;
        #pragma unroll
        for (int kk = 0; kk < 4; kk++) {
            uint32_t kb = kk*32;
            uint32_t af[4][4], bf[2][4];
            #pragma unroll
            for (int mt = 0; mt < 4; mt++)
                ldsm4(af[mt], aB + aRowOff + (uint32_t)(mt*16)*ROWB + kb);
            #pragma unroll
            for (int ng = 0; ng < 2; ng++)
                ldsm4(bf[ng], bB + bRowOff0 + (uint32_t)(ng*16)*ROWB + kb);
            #pragma unroll
            for (int mt = 0; mt < 4; mt++)
                #pragma unroll
                for (int nt = 0; nt < 4; nt++)
                    mma16816(acc[mt][nt], af[mt], &bf[nt >> 1][(nt & 1)*2]);
        }
        if (kt + 2 < NK) load_stage(kt + 2, (kt + 2) % 3);
        CP_COMMIT();
        if (kt + 1 < NK) { CP_WAIT1(); __syncthreads(); }
    }

    if (MODE == 0) {
        #pragma unroll
        for (int mt = 0; mt < 4; mt++) {
            int row = m0 + wm*64 + mt*16 + g;
            #pragma unroll
            for (int nt = 0; nt < 4; nt++) {
                int col = n0 + wn*32 + nt*8 + tig*2;
                float b0 = sbias[col - n0], b1 = sbias[col - n0 + 1];
                __nv_bfloat162 h0, h1;
                h0.x = __float2bfloat16_rn(acc[mt][nt][0] + b0);
                h0.y = __float2bfloat16_rn(acc[mt][nt][1] + b1);
                h1.x = __float2bfloat16_rn(acc[mt][nt][2] + b0);
                h1.y = __float2bfloat16_rn(acc[mt][nt][3] + b1);
                *(__nv_bfloat162*)&C[(size_t)row*HP + col] = h0;
                *(__nv_bfloat162*)&C[(size_t)(row+8)*HP + col] = h1;
            }
        }
    } else {
        #pragma unroll
        for (int mt = 0; mt < 4; mt++) {
            #pragma unroll
            for (int half = 0; half < 2; half++) {
                int j0 = n0 + wn*32 + half*16;
                int colA = j0 - n0 + tig*2, colB = j0 - n0 + 8 + tig*2;
                float bA0 = sbias[colA], bA1 = sbias[colA+1];
                float bB0 = sbias[colB], bB1 = sbias[colB+1];
                int nt0 = 2*half, nt1 = 2*half + 1;
                float vlo = fmaxf(fmaxf(acc[mt][nt0][0] + bA0, acc[mt][nt0][1] + bA1),
                                  fmaxf(acc[mt][nt1][0] + bB0, acc[mt][nt1][1] + bB1));
                float vhi = fmaxf(fmaxf(acc[mt][nt0][2] + bA0, acc[mt][nt0][3] + bA1),
                                  fmaxf(acc[mt][nt1][2] + bB0, acc[mt][nt1][3] + bB1));
                vlo = fmaxf(vlo, __shfl_xor_sync(0xffffffffu, vlo, 1));
                vlo = fmaxf(vlo, __shfl_xor_sync(0xffffffffu, vlo, 2));
                vhi = fmaxf(vhi, __shfl_xor_sync(0xffffffffu, vhi, 1));
                vhi = fmaxf(vhi, __shfl_xor_sync(0xffffffffu, vhi, 2));
                if (tig == 0) {
                    int row = m0 + wm*64 + mt*16 + g;
                    int ii = j0 >> 4;
                    C[(size_t)row*H_ + ii]     = __float2bfloat16_rn(vlo);
                    C[(size_t)(row+8)*H_ + ii] = __float2bfloat16_rn(vhi);
                }
            }
        }
    }
}

// ---------------- per-iteration small kernels ----------------
// fused r + d: grid B_, block 1024
__global__ void k_rd(int useEnd) {
    const float* WDt = useEnd ? g_WDeT : g_WDsT;
    const float* wrT = useEnd ? g_w1erT : g_w1srT;
    __shared__ float xs[5*H_];
    __shared__ float part[4][256];
    __shared__ float rs[256];
    int b = blockIdx.x;
    int tid = threadIdx.x;
    int h = tid & 255, ks = tid >> 8;   // 0..3
    for (int i = tid; i < 5*H_; i += 1024)
        xs[i] = (i < 256) ? g_hx[b*H_ + i]
              : (i < 768) ? g_encs[b*C2H + i - 256]
                          : g_ence[b*C2H + i - 768];
    __syncthreads();
    {
        float acc = 0.f;
        int k0 = ks*320;
        #pragma unroll 4
        for (int k = k0; k < k0 + 320; k++) acc += xs[k] * WDt[k*H_ + h];
        part[ks][h] = acc;
    }
    __syncthreads();
    if (ks == 0) {
        float rv = tanhf(part[0][h] + part[1][h] + part[2][h] + part[3][h]);
        rs[h] = rv;
        g_r[b*H_ + h] = rv;
    }
    __syncthreads();
    // d: 4 j per thread (j = tid + q*1024), 4 accumulators, unroll 4 -> MLP 16
    float a0 = 0.f, a1 = 0.f, a2 = 0.f, a3 = 0.f;
    #pragma unroll 4
    for (int k = 0; k < 256; k++) {
        float rv = rs[k];
        const float* w = wrT + (size_t)k*HP + tid;
        a0 = fmaf(rv, w[0],    a0);
        a1 = fmaf(rv, w[1024], a1);
        a2 = fmaf(rv, w[2048], a2);
        a3 = fmaf(rv, w[3072], a3);
    }
    g_d[b*HP + tid]        = a0;
    g_d[b*HP + tid + 1024] = a1;
    g_d[b*HP + tid + 2048] = a2;
    g_d[b*HP + tid + 3072] = a3;
}

__global__ void k_m1(int useEnd) {
    const __nv_bfloat16* Y = useEnd ? g_Y1e : g_Y1s;
    int b = blockIdx.x / (T_/8);
    int trow0 = (blockIdx.x % (T_/8)) * 8;
    int i = threadIdx.x;   // 256 threads
    float dv[16];
    const float4* drow = (const float4*)(g_d + b*HP + i*16);
    #pragma unroll
    for (int q = 0; q < 4; q++) {
        float4 f = drow[q];
        dv[q*4+0] = f.x; dv[q*4+1] = f.y; dv[q*4+2] = f.z; dv[q*4+3] = f.w;
    }
    for (int rr = 0; rr < 8; rr++) {
        int bt = b*T_ + trow0 + rr;
        const uint4* yy = (const uint4*)(Y + (size_t)bt*HP + i*16);
        uint4 u0 = yy[0], u1 = yy[1];
        uint32_t w[8] = {u0.x, u0.y, u0.z, u0.w, u1.x, u1.y, u1.z, u1.w};
        float mx = -1e30f;
        #pragma unroll
        for (int q = 0; q < 8; q++) {
            float2 f = __bfloat1622float2(*(__nv_bfloat162*)&w[q]);
            mx = fmaxf(mx, fmaxf(f.x + dv[2*q], f.y + dv[2*q+1]));
        }
        g_m1[bt*H_ + i] = __float2bfloat16_rn(mx);
    }
}

__global__ void k_m3(const float* __restrict__ w3, const float* __restrict__ b3,
                     const int* __restrict__ plen, float* __restrict__ out, int obase) {
    __shared__ float w3sm[16*512];
    __shared__ float b3sm[16];
    int tid = threadIdx.x;
    for (int idx = tid; idx < 16*512; idx += 256) w3sm[idx] = w3[idx];
    if (tid < 16) b3sm[tid] = b3[tid];
    __syncthreads();
    int w = tid >> 5, lane = tid & 31;
    int bt = blockIdx.x*8 + w;
    const __nv_bfloat16* m1r = g_m1 + (size_t)bt*H_;
    const __nv_bfloat16* m2r = g_m2a + (size_t)bt*H_;
    float acc[16];
    #pragma unroll
    for (int p = 0; p < 16; p++) acc[p] = 0.f;
    #pragma unroll
    for (int ki = 0; ki < 16; ki++) {
        int k = ki*32 + lane;
        float x = (ki < 8) ? __bfloat162float(m1r[k]) : __bfloat162float(m2r[k - 256]);
        #pragma unroll
        for (int p = 0; p < 16; p++) acc[p] += x * w3sm[p*512 + k];
    }
    #pragma unroll
    for (int p = 0; p < 16; p++)
        #pragma unroll
        for (int off = 16; off; off >>= 1)
            acc[p] += __shfl_down_sync(0xffffffffu, acc[p], off);
    if (lane == 0) {
        float s = -1e30f;
        #pragma unroll
        for (int p = 0; p < 16; p++) s = fmaxf(s, acc[p] + b3sm[p]);
        int b = bt >> 9, t = bt & 511;
        float a = s - ((t < plen[b]) ? 0.f : 1e9f);
        g_scores[bt] = a;
        out[obase + bt] = a;
    }
}

// ---------------- exact rescore path ----------------
__global__ void k_cand(int phase) {
    __shared__ float sv[512];
    int b = blockIdx.x, t = threadIdx.x;
    float v = g_scores[b*T_ + t];
    sv[t] = v; __syncthreads();
    for (int s = 256; s; s >>= 1) {
        if (t < s) sv[t] = fmaxf(sv[t], sv[t+s]);
        __syncthreads();
    }
    float thresh = sv[0] - MARGIN;
    if (v >= thresh) {
        int pos = atomicAdd(&g_ncand8[phase], 1);
        if (pos < CAP) g_cands[pos] = b*T_ + t;
    }
}

__global__ __launch_bounds__(256)
void k_ex1(const float* __restrict__ w1, const float* __restrict__ b1, int phase) {
    __shared__ float er[8][768];
    __shared__ float wt[256][20];
    int nc = min(g_ncand8[phase], CAP);
    int cbase = blockIdx.y * 8;
    if (cbase >= nc) return;
    int ncl = min(8, nc - cbase);
    int tid = threadIdx.x;
    for (int c = 0; c < ncl; c++) {
        int bt = g_cands[cbase + c];
        int b = bt >> 9;
        for (int idx = tid; idx < 768; idx += 256)
            er[c][idx] = (idx < 512) ? g_Etf[(size_t)bt*C2H + idx] : g_r[b*H_ + idx - 512];
    }
    __syncthreads();
    int j = blockIdx.x*256 + tid;
    float acc[8];
    #pragma unroll
    for (int c = 0; c < 8; c++) acc[c] = 0.f;
    for (int k0 = 0; k0 < 768; k0 += 16) {
        __syncthreads();
        const float4* src = (const float4*)&w1[(size_t)j*768 + k0];
        float4* dst = (float4*)&wt[tid][0];
        dst[0] = src[0]; dst[1] = src[1]; dst[2] = src[2]; dst[3] = src[3];
        __syncthreads();
        #pragma unroll
        for (int kk = 0; kk < 16; kk++) {
            float wv = wt[tid][kk];
            #pragma unroll
            for (int c = 0; c < 8; c++) acc[c] += er[c][k0+kk] * wv;
        }
    }
    float bb = b1[j];
    for (int c = 0; c < ncl; c++) {
        float v = acc[c] + bb;
        #pragma unroll
        for (int o = 1; o < 16; o <<= 1)
            v = fmaxf(v, __shfl_xor_sync(0xffffffffu, v, o));
        if ((tid & 15) == 0)
            g_m1x[(cbase+c)*H_ + (j >> 4)] = v;
    }
}

__global__ __launch_bounds__(256)
void k_ex2(const float* __restrict__ w2, const float* __restrict__ b2, int phase) {
    __shared__ float er[8][256];
    __shared__ float wt[256][20];
    int nc = min(g_ncand8[phase], CAP);
    int cbase = blockIdx.y * 8;
    if (cbase >= nc) return;
    int ncl = min(8, nc - cbase);
    int tid = threadIdx.x;
    for (int c = 0; c < ncl; c++)
        er[c][tid] = g_m1x[(cbase+c)*H_ + tid];
    __syncthreads();
    int j = blockIdx.x*256 + tid;
    float acc[8];
    #pragma unroll
    for (int c = 0; c < 8; c++) acc[c] = 0.f;
    for (int k0 = 0; k0 < 256; k0 += 16) {
        __syncthreads();
        const float4* src = (const float4*)&w2[(size_t)j*256 + k0];
        float4* dst = (float4*)&wt[tid][0];
        dst[0] = src[0]; dst[1] = src[1]; dst[2] = src[2]; dst[3] = src[3];
        __syncthreads();
        #pragma unroll
        for (int kk = 0; kk < 16; kk++) {
            float wv = wt[tid][kk];
            #pragma unroll
            for (int c = 0; c < 8; c++) acc[c] += er[c][k0+kk] * wv;
        }
    }
    float bb = b2[j];
    for (int c = 0; c < ncl; c++) {
        float v = acc[c] + bb;
        #pragma unroll
        for (int o = 1; o < 16; o <<= 1)
            v = fmaxf(v, __shfl_xor_sync(0xffffffffu, v, o));
        if ((tid & 15) == 0)
            g_m2x[(cbase+c)*H_ + (j >> 4)] = v;
    }
}

__global__ __launch_bounds__(256)
void k_ex3(const float* __restrict__ w3, const float* __restrict__ b3, int phase) {
    __shared__ float w3sm[16*512];
    int nc = min(g_ncand8[phase], CAP);
    int tid = threadIdx.x;
    int c = blockIdx.x*8 + (tid >> 5);
    int lane = tid & 31;
    if (blockIdx.x*8 >= nc) return;
    for (int idx = tid; idx < 16*512; idx += 256) w3sm[idx] = w3[idx];
    __syncthreads();
    if (c >= nc) return;
    float acc[16];
    #pragma unroll
    for (int p = 0; p < 16; p++) acc[p] = 0.f;
    #pragma unroll
    for (int ki = 0; ki < 16; ki++) {
        int k = ki*32 + lane;
        float x = (ki < 8) ? g_m1x[c*H_ + k] : g_m2x[c*H_ + k - 256];
        #pragma unroll
        for (int p = 0; p < 16; p++) acc[p] += x * w3sm[p*512 + k];
    }
    #pragma unroll
    for (int p = 0; p < 16; p++)
        #pragma unroll
        for (int off = 16; off; off >>= 1)
            acc[p] += __shfl_down_sync(0xffffffffu, acc[p], off);
    if (lane == 0) {
        float s = -1e30f;
        #pragma unroll
        for (int p = 0; p < 16; p++) s = fmaxf(s, acc[p] + b3[p]);
        g_sexact[c] = s;
    }
}

__global__ void k_argmax2(const float* __restrict__ enc, float* __restrict__ out,
                          int outoff, int useEnd, int phase) {
    __shared__ float sv[512];
    __shared__ int   si[512];
    __shared__ int   sidx;
    int b = blockIdx.x, tid = threadIdx.x;
    int nc = min(g_ncand8[phase], CAP);
    float best = -1e30f; int bi = 1 << 30;
    for (int i = tid; i < nc; i += 512) {
        int bt = g_cands[i];
        if ((bt >> 9) == b) {
            float v = g_sexact[i]; int t = bt & 511;
            if (v > best || (v == best && t < bi)) { best = v; bi = t; }
        }
    }
    sv[tid] = best; si[tid] = bi;
    __syncthreads();
    for (int s = 256; s; s >>= 1) {
        if (tid < s) {
            float v2 = sv[tid+s]; int i2 = si[tid+s];
            if (v2 > sv[tid] || (v2 == sv[tid] && i2 < si[tid])) { sv[tid] = v2; si[tid] = i2; }
        }
        __syncthreads();
    }
    if (tid == 0) { sidx = si[0]; out[outoff + b] = (float)si[0]; }
    __syncthreads();
    int idx = sidx;
    float* sel = useEnd ? g_ence : g_encs;
    sel[b*C2H + tid] = enc[(size_t)b*C2H*T_ + (size_t)tid*T_ + idx];
}

__device__ __forceinline__ float sigf(float x) { return 1.f / (1.f + expf(-x)); }

// fused LSTM gates + cell + MLP, ILP-optimized
__global__ void k_lstmfused(const float* __restrict__ bih, const float* __restrict__ bhh,
                            const float* __restrict__ bmlp) {
    __shared__ float xs[1024];
    __shared__ float hs[256];
    __shared__ float hp[256];
    __shared__ float gsm[1024];
    __shared__ float part[4][256];
    int b = blockIdx.x, j = threadIdx.x;  // 1024 threads
    xs[j] = (j < 512) ? g_encs[b*C2H + j] : g_ence[b*C2H + j - 512];
    if (j < 256) hs[j] = g_hx[b*H_ + j];
    __syncthreads();
    float a0 = 0.f, a1 = 0.f, a2 = 0.f, a3 = 0.f;
    #pragma unroll 4
    for (int k = 0; k < 1024; k += 4) {
        a0 = fmaf(xs[k],   g_WihT[(size_t)k*1024 + j],       a0);
        a1 = fmaf(xs[k+1], g_WihT[(size_t)(k+1)*1024 + j],   a1);
        a2 = fmaf(xs[k+2], g_WihT[(size_t)(k+2)*1024 + j],   a2);
        a3 = fmaf(xs[k+3], g_WihT[(size_t)(k+3)*1024 + j],   a3);
    }
    #pragma unroll 4
    for (int k = 0; k < 256; k += 4) {
        a0 = fmaf(hs[k],   g_WhhT[(size_t)k*1024 + j],       a0);
        a1 = fmaf(hs[k+1], g_WhhT[(size_t)(k+1)*1024 + j],   a1);
        a2 = fmaf(hs[k+2], g_WhhT[(size_t)(k+2)*1024 + j],   a2);
        a3 = fmaf(hs[k+3], g_WhhT[(size_t)(k+3)*1024 + j],   a3);
    }
    gsm[j] = bih[j] + bhh[j] + (a0 + a1) + (a2 + a3);
    __syncthreads();
    if (j < 256) {
        float i_ = gsm[j], f_ = gsm[256 + j], gg = gsm[512 + j], o_ = gsm[768 + j];
        float c = sigf(f_) * g_cx[b*H_ + j] + sigf(i_) * tanhf(gg);
        g_cx[b*H_ + j] = c;
        hp[j] = sigf(o_) * tanhf(c);
    }
    __syncthreads();
    // MLP with 4-way k-split: all 1024 threads active
    {
        int h = j & 255, ks = j >> 8;
        float m = 0.f;
        int k0 = ks*64;
        #pragma unroll 8
        for (int k = k0; k < k0 + 64; k++)
            m = fmaf(hp[k], g_WmlpT[k*H_ + h], m);
        part[ks][h] = m;
    }
    __syncthreads();
    if (j < 256)
        g_hx[b*H_ + j] = bmlp[j] + (part[0][j] + part[1][j]) + (part[2][j] + part[3][j]);
}

// ---------------- launch ----------------
extern "C" void kernel_launch(void* const* d_in, const int* in_sizes, int n_in,
                              void* d_out, int out_size) {
    const float* enc  = (const float*)d_in[0];
    const int*   plen = (const int*)d_in[1];
    const float* WDs  = (const float*)d_in[2];
    const float* w1s  = (const float*)d_in[3];
    const float* b1s  = (const float*)d_in[4];
    const float* w2s  = (const float*)d_in[5];
    const float* b2s  = (const float*)d_in[6];
    const float* w3s  = (const float*)d_in[7];
    const float* b3s  = (const float*)d_in[8];
    const float* WDe  = (const float*)d_in[9];
    const float* w1e  = (const float*)d_in[10];
    const float* b1e  = (const float*)d_in[11];
    const float* w2e  = (const float*)d_in[12];
    const float* b2e  = (const float*)d_in[13];
    const float* w3e  = (const float*)d_in[14];
    const float* b3e  = (const float*)d_in[15];
    const float* Wih  = (const float*)d_in[16];
    const float* Whh  = (const float*)d_in[17];
    const float* bih  = (const float*)d_in[18];
    const float* bhh  = (const float*)d_in[19];
    const float* Wmlp = (const float*)d_in[20];
    const float* bmlp = (const float*)d_in[21];
    float* out = (float*)d_out;

    cudaFuncSetAttribute(gemm_cp<0>, cudaFuncAttributeMaxDynamicSharedMemorySize, GEMM_DSMEM);
    cudaFuncSetAttribute(gemm_cp<1>, cudaFuncAttributeMaxDynamicSharedMemorySize, GEMM_DSMEM);

    dim3 ggrid(HP/128, M_/128);   // (32, 128)

    k_init<<<B_, 512>>>(enc);                          // 0
    {
        dim3 g(16, 16, B_), blk(32, 8);
        k_tEt<<<g, blk>>>(enc);                        // 1
    }
    k_w1prep<<<2048, 256>>>(w1s, 0);                   // 2
    gemm_cp<0><<<ggrid, 256, GEMM_DSMEM>>>(b1s, 0);    // 3
    k_w1prep<<<2048, 256>>>(w1e, 1);                   // 4
    gemm_cp<0><<<ggrid, 256, GEMM_DSMEM>>>(b1e, 1);    // 5
    k_w2prep<<<1024, 256>>>(w2s, 0);
    k_w2prep<<<1024, 256>>>(w2e, 1);
    k_WDprep<<<512, 256>>>(WDs, 0);
    k_WDprep<<<512, 256>>>(WDe, 1);
    k_lstmprep<<<2048, 256>>>(Wih, Whh, Wmlp);

    const int ALPHA0 = 64;
    const int BETA0  = 64 + NITER*M_;
    dim3 exg(16, CAP/8);   // (16, 64)

    for (int it = 0; it < NITER; it++) {
        int phS = it*2, phE = it*2 + 1;
        // ---- start phase ----
        k_rd<<<B_, 1024>>>(0);
        k_m1<<<B_*(T_/8), 256>>>(0);
        gemm_cp<1><<<ggrid, 256, GEMM_DSMEM>>>(b2s, 0);
        k_m3<<<M_/8, 256>>>(w3s, b3s, plen, out, ALPHA0 + it*M_);
        k_cand<<<B_, 512>>>(phS);
        k_ex1<<<exg, 256>>>(w1s, b1s, phS);
        k_ex2<<<exg, 256>>>(w2s, b2s, phS);
        k_ex3<<<CAP/8, 256>>>(w3s, b3s, phS);
        k_argmax2<<<B_, 512>>>(enc, out, 0, 0, phS);
        // ---- end phase ----
        k_rd<<<B_, 1024>>>(1);
        k_m1<<<B_*(T_/8), 256>>>(1);
        gemm_cp<1><<<ggrid, 256, GEMM_DSMEM>>>(b2e, 1);
        k_m3<<<M_/8, 256>>>(w3e, b3e, plen, out, BETA0 + it*M_);
        k_cand<<<B_, 512>>>(phE);
        k_ex1<<<exg, 256>>>(w1e, b1e, phE);
        k_ex2<<<exg, 256>>>(w2e, b2e, phE);
        k_ex3<<<CAP/8, 256>>>(w3e, b3e, phE);
        k_argmax2<<<B_, 512>>>(enc, out, 32, 1, phE);
        // ---- LSTM + MLP (fused) ----
        k_lstmfused<<<B_, 1024>>>(bih, bhh, bmlp);
    }
}

// round 17
// speedup vs baseline: 1.4552x; 1.4552x over previous
#include <cuda_runtime.h>
#include <cuda_bf16.h>
#include <math.h>
#include <stdint.h>

#define B_    32
#define T_    512
#define H_    256
#define C2H   512        // 2H
#define HP    4096       // H*P
#define M_    (B_*T_)    // 16384 rows
#define NITER 4
#define CAP   512        // max rescore candidates per phase
#define MARGIN 0.015f

// ---------------- static device buffers (no dynamic alloc) ----------------
__device__ __align__(128) __nv_bfloat16 g_Et[(size_t)M_*C2H];
__device__ __align__(128) float         g_Etf[(size_t)M_*C2H];
__device__ __align__(128) __nv_bfloat16 g_Y1s[(size_t)M_*HP];          // 128MB
__device__ __align__(128) __nv_bfloat16 g_Y1e[(size_t)M_*HP];          // 128MB
__device__ __align__(128) __nv_bfloat16 g_w1sb[HP*C2H];
__device__ __align__(128) __nv_bfloat16 g_w1eb[HP*C2H];
__device__ __align__(128) float         g_w1srT[H_*HP];
__device__ __align__(128) float         g_w1erT[H_*HP];
__device__ __align__(128) __nv_bfloat16 g_w2sb[HP*H_];
__device__ __align__(128) __nv_bfloat16 g_w2eb[HP*H_];
__device__ float         g_WDsT[5*H_*H_];
__device__ float         g_WDeT[5*H_*H_];
__device__ float         g_WihT[1024*1024];
__device__ float         g_WhhT[H_*1024];
__device__ float         g_WmlpT[H_*H_];
__device__ __align__(128) __nv_bfloat16 g_m1[M_*H_];
__device__ __align__(128) __nv_bfloat16 g_m2a[M_*H_];
__device__ float         g_scores[M_];
__device__ float         g_hx[B_*H_], g_cx[B_*H_];
__device__ float         g_encs[B_*C2H], g_ence[B_*C2H];
__device__ float         g_r[B_*H_];
__device__ __align__(16) float g_d[B_*HP];
// exact-rescore scratch
__device__ int           g_ncand8[8];
__device__ int           g_cands[CAP];
__device__ float         g_m1x[CAP*H_];
__device__ float         g_m2x[CAP*H_];
__device__ float         g_sexact[CAP];

// ---------------- helpers ----------------
__device__ __forceinline__ uint32_t smem_u32(const void* p) {
    uint32_t a;
    asm("{ .reg .u64 t; cvta.to.shared.u64 t, %1; cvt.u32.u64 %0, t; }" : "=r"(a) : "l"(p));
    return a;
}
__device__ __forceinline__ void cp16(uint32_t smem, const void* g) {
    asm volatile("cp.async.cg.shared.global [%0], [%1], 16;" :: "r"(smem), "l"(g) : "memory");
}
#define CP_COMMIT() asm volatile("cp.async.commit_group;" ::: "memory")
#define CP_WAIT1()  asm volatile("cp.async.wait_group 1;" ::: "memory")
__device__ __forceinline__ void ldsm4(uint32_t* r, uint32_t addr) {
    asm volatile("ldmatrix.sync.aligned.m8n8.x4.shared.b16 {%0,%1,%2,%3}, [%4];"
        : "=r"(r[0]), "=r"(r[1]), "=r"(r[2]), "=r"(r[3]) : "r"(addr));
}
__device__ __forceinline__ void mma16816(float* c, const uint32_t* a, const uint32_t* b) {
    asm volatile(
        "mma.sync.aligned.m16n8k16.row.col.f32.bf16.bf16.f32 "
        "{%0,%1,%2,%3}, {%4,%5,%6,%7}, {%8,%9}, {%0,%1,%2,%3};\n"
        : "+f"(c[0]), "+f"(c[1]), "+f"(c[2]), "+f"(c[3])
        : "r"(a[0]), "r"(a[1]), "r"(a[2]), "r"(a[3]), "r"(b[0]), "r"(b[1]));
}

// ---------------- prep kernels ----------------
__global__ void k_init(const float* __restrict__ enc) {
    int b = blockIdx.x, c = threadIdx.x;   // 512 threads
    float v = enc[(size_t)b*C2H*T_ + (size_t)c*T_ + 0];
    g_encs[b*C2H + c] = v;
    g_ence[b*C2H + c] = v;
    if (c < H_) { g_hx[b*H_ + c] = 0.f; g_cx[b*H_ + c] = 0.f; }
    if (b == 0 && c < 8) g_ncand8[c] = 0;
}

__global__ void k_tEt(const float* __restrict__ enc) {
    __shared__ float tile[32][33];
    int b = blockIdx.z;
    int t0 = blockIdx.x*32, c0 = blockIdx.y*32;
    for (int i = threadIdx.y; i < 32; i += 8)
        tile[i][threadIdx.x] = enc[(size_t)b*C2H*T_ + (size_t)(c0+i)*T_ + t0 + threadIdx.x];
    __syncthreads();
    for (int i = threadIdx.y; i < 32; i += 8) {
        float v = tile[threadIdx.x][i];
        size_t o = (size_t)b*T_*C2H + (size_t)(t0+i)*C2H + c0 + threadIdx.x;
        g_Et[o]  = __float2bfloat16_rn(v);
        g_Etf[o] = v;
    }
}

__global__ void k_w1prep(const float* __restrict__ w1, int useEnd) {
    __nv_bfloat16* wb = useEnd ? g_w1eb : g_w1sb;
    float* wrT = useEnd ? g_w1erT : g_w1srT;
    int total0 = HP*C2H;
    for (int idx = blockIdx.x*blockDim.x + threadIdx.x; idx < total0; idx += gridDim.x*blockDim.x) {
        int j = idx / C2H, k = idx % C2H;
        wb[idx] = __float2bfloat16_rn(w1[(size_t)j*768 + k]);
    }
    int total1 = H_*HP;
    for (int idx = blockIdx.x*blockDim.x + threadIdx.x; idx < total1; idx += gridDim.x*blockDim.x) {
        int k = idx / HP, j = idx % HP;
        wrT[idx] = w1[(size_t)j*768 + 512 + k];
    }
}

__global__ void k_w2prep(const float* __restrict__ w2, int useEnd) {
    __nv_bfloat16* out = useEnd ? g_w2eb : g_w2sb;
    int total = HP*H_;
    for (int idx = blockIdx.x*blockDim.x + threadIdx.x; idx < total; idx += gridDim.x*blockDim.x)
        out[idx] = __float2bfloat16_rn(w2[idx]);
}

__global__ void k_WDprep(const float* __restrict__ WD, int useEnd) {
    float* out = useEnd ? g_WDeT : g_WDsT;
    int total = 5*H_*H_;
    for (int idx = blockIdx.x*blockDim.x + threadIdx.x; idx < total; idx += gridDim.x*blockDim.x) {
        int k = idx / H_, h = idx % H_;
        out[idx] = WD[(size_t)h*(5*H_) + k];
    }
}

__global__ void k_lstmprep(const float* __restrict__ Wih, const float* __restrict__ Whh,
                           const float* __restrict__ Wmlp) {
    int stride = gridDim.x*blockDim.x;
    for (int idx = blockIdx.x*blockDim.x + threadIdx.x; idx < 1024*1024; idx += stride) {
        int k = idx / 1024, j = idx % 1024;
        g_WihT[idx] = Wih[(size_t)j*1024 + k];
    }
    for (int idx = blockIdx.x*blockDim.x + threadIdx.x; idx < H_*1024; idx += stride) {
        int k = idx / 1024, j = idx % 1024;
        g_WhhT[idx] = Whh[(size_t)j*H_ + k];
    }
    for (int idx = blockIdx.x*blockDim.x + threadIdx.x; idx < H_*H_; idx += stride) {
        int k = idx / H_, j = idx % H_;
        g_WmlpT[idx] = Wmlp[(size_t)j*H_ + k];
    }
}

// ---------------- pipelined mma.sync GEMM (3-stage) ----------------
#define ROWB    144
#define STAGE_A (128*ROWB)
#define STAGE_BYTES (2*STAGE_A)
#define GEMM_DSMEM (3*STAGE_BYTES)

template<int MODE>
__global__ __launch_bounds__(256, 2)
void gemm_cp(const float* __restrict__ bias, int useEnd) {
    constexpr int K  = (MODE == 0) ? 512 : 256;
    constexpr int NK = K / 64;
    const __nv_bfloat16* A  = (MODE == 0) ? g_Et : g_m1;
    const __nv_bfloat16* Bm = (MODE == 0) ? (useEnd ? g_w1eb : g_w1sb)
                                          : (useEnd ? g_w2eb : g_w2sb);
    __nv_bfloat16* C        = (MODE == 0) ? (useEnd ? g_Y1e : g_Y1s) : g_m2a;

    extern __shared__ __align__(16) char dynsm[];
    uint32_t smbase = smem_u32(dynsm);
    __shared__ float sbias[128];

    int tid = threadIdx.x, wid = tid >> 5, lane = tid & 31;
    int m0 = blockIdx.y*128, n0 = blockIdx.x*128;
    int wm = wid >> 2, wn = wid & 3;
    int g = lane >> 2, tig = lane & 3;
    int l7 = lane & 7, sel = lane >> 3;

    if (tid < 128) sbias[tid] = bias[n0 + tid];

    float acc[4][4][4];
    #pragma unroll
    for (int a = 0; a < 4; a++)
        #pragma unroll
        for (int bq = 0; bq < 4; bq++)
            #pragma unroll
            for (int cq = 0; cq < 4; cq++) acc[a][bq][cq] = 0.f;

    auto load_stage = [&](int kt, int buf) {
        uint32_t sb = smbase + buf*STAGE_BYTES;
        #pragma unroll
        for (int i = 0; i < 8; i++) {
            int q = tid + (i & 3)*256;
            int r_ = q >> 3, c = q & 7;
            if (i < 4)
                cp16(sb + r_*ROWB + c*16, &A[(size_t)(m0+r_)*K + kt*64 + c*8]);
            else
                cp16(sb + STAGE_A + r_*ROWB + c*16, &Bm[(size_t)(n0+r_)*K + kt*64 + c*8]);
        }
    };

    load_stage(0, 0); CP_COMMIT();
    load_stage(1, 1); CP_COMMIT();
    CP_WAIT1();
    __syncthreads();

    uint32_t aRowOff = (uint32_t)(wm*64 + l7 + (sel & 1)*8) * ROWB + (uint32_t)(sel >> 1)*16;
    uint32_t bRowOff0 = (uint32_t)(wn*32 + l7 + (sel >> 1)*8) * ROWB + (uint32_t)(sel & 1)*16;

    for (int kt = 0; kt < NK; kt++) {
        uint32_t aB = smbase + (kt % 3)*STAGE_BYTES;
        uint32_t bB = aB + STAGE_A;
        #pragma unroll
        for (int kk = 0; kk < 4; kk++) {
            uint32_t kb = kk*32;
            uint32_t af[4][4], bf[2][4];
            #pragma unroll
            for (int mt = 0; mt < 4; mt++)
                ldsm4(af[mt], aB + aRowOff + (uint32_t)(mt*16)*ROWB + kb);
            #pragma unroll
            for (int ng = 0; ng < 2; ng++)
                ldsm4(bf[ng], bB + bRowOff0 + (uint32_t)(ng*16)*ROWB + kb);
            #pragma unroll
            for (int mt = 0; mt < 4; mt++)
                #pragma unroll
                for (int nt = 0; nt < 4; nt++)
                    mma16816(acc[mt][nt], af[mt], &bf[nt >> 1][(nt & 1)*2]);
        }
        if (kt + 2 < NK) load_stage(kt + 2, (kt + 2) % 3);
        CP_COMMIT();
        if (kt + 1 < NK) { CP_WAIT1(); __syncthreads(); }
    }

    if (MODE == 0) {
        #pragma unroll
        for (int mt = 0; mt < 4; mt++) {
            int row = m0 + wm*64 + mt*16 + g;
            #pragma unroll
            for (int nt = 0; nt < 4; nt++) {
                int col = n0 + wn*32 + nt*8 + tig*2;
                float b0 = sbias[col - n0], b1 = sbias[col - n0 + 1];
                __nv_bfloat162 h0, h1;
                h0.x = __float2bfloat16_rn(acc[mt][nt][0] + b0);
                h0.y = __float2bfloat16_rn(acc[mt][nt][1] + b1);
                h1.x = __float2bfloat16_rn(acc[mt][nt][2] + b0);
                h1.y = __float2bfloat16_rn(acc[mt][nt][3] + b1);
                *(__nv_bfloat162*)&C[(size_t)row*HP + col] = h0;
                *(__nv_bfloat162*)&C[(size_t)(row+8)*HP + col] = h1;
            }
        }
    } else {
        #pragma unroll
        for (int mt = 0; mt < 4; mt++) {
            #pragma unroll
            for (int half = 0; half < 2; half++) {
                int j0 = n0 + wn*32 + half*16;
                int colA = j0 - n0 + tig*2, colB = j0 - n0 + 8 + tig*2;
                float bA0 = sbias[colA], bA1 = sbias[colA+1];
                float bB0 = sbias[colB], bB1 = sbias[colB+1];
                int nt0 = 2*half, nt1 = 2*half + 1;
                float vlo = fmaxf(fmaxf(acc[mt][nt0][0] + bA0, acc[mt][nt0][1] + bA1),
                                  fmaxf(acc[mt][nt1][0] + bB0, acc[mt][nt1][1] + bB1));
                float vhi = fmaxf(fmaxf(acc[mt][nt0][2] + bA0, acc[mt][nt0][3] + bA1),
                                  fmaxf(acc[mt][nt1][2] + bB0, acc[mt][nt1][3] + bB1));
                vlo = fmaxf(vlo, __shfl_xor_sync(0xffffffffu, vlo, 1));
                vlo = fmaxf(vlo, __shfl_xor_sync(0xffffffffu, vlo, 2));
                vhi = fmaxf(vhi, __shfl_xor_sync(0xffffffffu, vhi, 1));
                vhi = fmaxf(vhi, __shfl_xor_sync(0xffffffffu, vhi, 2));
                if (tig == 0) {
                    int row = m0 + wm*64 + mt*16 + g;
                    int ii = j0 >> 4;
                    C[(size_t)row*H_ + ii]     = __float2bfloat16_rn(vlo);
                    C[(size_t)(row+8)*H_ + ii] = __float2bfloat16_rn(vhi);
                }
            }
        }
    }
}

// ---------------- per-iteration small kernels ----------------
__global__ void k_r(int useEnd) {   // grid B_, block 1024 (4-way k-split)
    const float* WDt = useEnd ? g_WDeT : g_WDsT;
    __shared__ float xs[5*H_];
    __shared__ float part[4][256];
    int b = blockIdx.x;
    int tid = threadIdx.x;
    int h = tid & 255, ks = tid >> 8;   // 0..3
    for (int i = tid; i < 5*H_; i += 1024)
        xs[i] = (i < 256) ? g_hx[b*H_ + i]
              : (i < 768) ? g_encs[b*C2H + i - 256]
                          : g_ence[b*C2H + i - 768];
    __syncthreads();
    float acc = 0.f;
    int k0 = ks*320;
    #pragma unroll 4
    for (int k = k0; k < k0 + 320; k++) acc += xs[k] * WDt[k*H_ + h];
    part[ks][h] = acc;
    __syncthreads();
    if (ks == 0)
        g_r[b*H_ + h] = tanhf(part[0][h] + part[1][h] + part[2][h] + part[3][h]);
}

__global__ void k_d(int useEnd) {    // grid (16, 32), block 256
    const float* wrT = useEnd ? g_w1erT : g_w1srT;
    int b = blockIdx.y, j = blockIdx.x*256 + threadIdx.x;
    __shared__ float rs[H_];
    rs[threadIdx.x] = g_r[b*H_ + threadIdx.x];
    __syncthreads();
    float acc = 0.f;
    #pragma unroll 4
    for (int k = 0; k < H_; k++) acc += rs[k] * wrT[k*HP + j];
    g_d[b*HP + j] = acc;
}

__global__ void k_m1(int useEnd) {
    const __nv_bfloat16* Y = useEnd ? g_Y1e : g_Y1s;
    int b = blockIdx.x / (T_/8);
    int trow0 = (blockIdx.x % (T_/8)) * 8;
    int i = threadIdx.x;   // 256 threads
    float dv[16];
    const float4* drow = (const float4*)(g_d + b*HP + i*16);
    #pragma unroll
    for (int q = 0; q < 4; q++) {
        float4 f = drow[q];
        dv[q*4+0] = f.x; dv[q*4+1] = f.y; dv[q*4+2] = f.z; dv[q*4+3] = f.w;
    }
    for (int rr = 0; rr < 8; rr++) {
        int bt = b*T_ + trow0 + rr;
        const uint4* yy = (const uint4*)(Y + (size_t)bt*HP + i*16);
        uint4 u0 = yy[0], u1 = yy[1];
        uint32_t w[8] = {u0.x, u0.y, u0.z, u0.w, u1.x, u1.y, u1.z, u1.w};
        float mx = -1e30f;
        #pragma unroll
        for (int q = 0; q < 8; q++) {
            float2 f = __bfloat1622float2(*(__nv_bfloat162*)&w[q]);
            mx = fmaxf(mx, fmaxf(f.x + dv[2*q], f.y + dv[2*q+1]));
        }
        g_m1[bt*H_ + i] = __float2bfloat16_rn(mx);
    }
}

__global__ void k_m3(const float* __restrict__ w3, const float* __restrict__ b3,
                     const int* __restrict__ plen, float* __restrict__ out, int obase) {
    __shared__ float w3sm[16*512];
    __shared__ float b3sm[16];
    int tid = threadIdx.x;
    for (int idx = tid; idx < 16*512; idx += 256) w3sm[idx] = w3[idx];
    if (tid < 16) b3sm[tid] = b3[tid];
    __syncthreads();
    int w = tid >> 5, lane = tid & 31;
    int bt = blockIdx.x*8 + w;
    const __nv_bfloat16* m1r = g_m1 + (size_t)bt*H_;
    const __nv_bfloat16* m2r = g_m2a + (size_t)bt*H_;
    float acc[16];
    #pragma unroll
    for (int p = 0; p < 16; p++) acc[p] = 0.f;
    #pragma unroll
    for (int ki = 0; ki < 16; ki++) {
        int k = ki*32 + lane;
        float x = (ki < 8) ? __bfloat162float(m1r[k]) : __bfloat162float(m2r[k - 256]);
        #pragma unroll
        for (int p = 0; p < 16; p++) acc[p] += x * w3sm[p*512 + k];
    }
    #pragma unroll
    for (int p = 0; p < 16; p++)
        #pragma unroll
        for (int off = 16; off; off >>= 1)
            acc[p] += __shfl_down_sync(0xffffffffu, acc[p], off);
    if (lane == 0) {
        float s = -1e30f;
        #pragma unroll
        for (int p = 0; p < 16; p++) s = fmaxf(s, acc[p] + b3sm[p]);
        int b = bt >> 9, t = bt & 511;
        float a = s - ((t < plen[b]) ? 0.f : 1e9f);
        g_scores[bt] = a;
        out[obase + bt] = a;
    }
}

// ---------------- exact rescore path ----------------
__global__ void k_cand(int phase) {
    __shared__ float sv[512];
    int b = blockIdx.x, t = threadIdx.x;
    float v = g_scores[b*T_ + t];
    sv[t] = v; __syncthreads();
    for (int s = 256; s; s >>= 1) {
        if (t < s) sv[t] = fmaxf(sv[t], sv[t+s]);
        __syncthreads();
    }
    float thresh = sv[0] - MARGIN;
    if (v >= thresh) {
        int pos = atomicAdd(&g_ncand8[phase], 1);
        if (pos < CAP) g_cands[pos] = b*T_ + t;
    }
}

__global__ __launch_bounds__(256)
void k_ex1(const float* __restrict__ w1, const float* __restrict__ b1, int phase) {
    __shared__ float er[8][768];
    __shared__ float wt[256][20];
    int nc = min(g_ncand8[phase], CAP);
    int cbase = blockIdx.y * 8;
    if (cbase >= nc) return;
    int ncl = min(8, nc - cbase);
    int tid = threadIdx.x;
    for (int c = 0; c < ncl; c++) {
        int bt = g_cands[cbase + c];
        int b = bt >> 9;
        for (int idx = tid; idx < 768; idx += 256)
            er[c][idx] = (idx < 512) ? g_Etf[(size_t)bt*C2H + idx] : g_r[b*H_ + idx - 512];
    }
    __syncthreads();
    int j = blockIdx.x*256 + tid;
    float acc[8];
    #pragma unroll
    for (int c = 0; c < 8; c++) acc[c] = 0.f;
    for (int k0 = 0; k0 < 768; k0 += 16) {
        __syncthreads();
        const float4* src = (const float4*)&w1[(size_t)j*768 + k0];
        float4* dst = (float4*)&wt[tid][0];
        dst[0] = src[0]; dst[1] = src[1]; dst[2] = src[2]; dst[3] = src[3];
        __syncthreads();
        #pragma unroll
        for (int kk = 0; kk < 16; kk++) {
            float wv = wt[tid][kk];
            #pragma unroll
            for (int c = 0; c < 8; c++) acc[c] += er[c][k0+kk] * wv;
        }
    }
    float bb = b1[j];
    for (int c = 0; c < ncl; c++) {
        float v = acc[c] + bb;
        #pragma unroll
        for (int o = 1; o < 16; o <<= 1)
            v = fmaxf(v, __shfl_xor_sync(0xffffffffu, v, o));
        if ((tid & 15) == 0)
            g_m1x[(cbase+c)*H_ + (j >> 4)] = v;
    }
}

__global__ __launch_bounds__(256)
void k_ex2(const float* __restrict__ w2, const float* __restrict__ b2, int phase) {
    __shared__ float er[8][256];
    __shared__ float wt[256][20];
    int nc = min(g_ncand8[phase], CAP);
    int cbase = blockIdx.y * 8;
    if (cbase >= nc) return;
    int ncl = min(8, nc - cbase);
    int tid = threadIdx.x;
    for (int c = 0; c < ncl; c++)
        er[c][tid] = g_m1x[(cbase+c)*H_ + tid];
    __syncthreads();
    int j = blockIdx.x*256 + tid;
    float acc[8];
    #pragma unroll
    for (int c = 0; c < 8; c++) acc[c] = 0.f;
    for (int k0 = 0; k0 < 256; k0 += 16) {
        __syncthreads();
        const float4* src = (const float4*)&w2[(size_t)j*256 + k0];
        float4* dst = (float4*)&wt[tid][0];
        dst[0] = src[0]; dst[1] = src[1]; dst[2] = src[2]; dst[3] = src[3];
        __syncthreads();
        #pragma unroll
        for (int kk = 0; kk < 16; kk++) {
            float wv = wt[tid][kk];
            #pragma unroll
            for (int c = 0; c < 8; c++) acc[c] += er[c][k0+kk] * wv;
        }
    }
    float bb = b2[j];
    for (int c = 0; c < ncl; c++) {
        float v = acc[c] + bb;
        #pragma unroll
        for (int o = 1; o < 16; o <<= 1)
            v = fmaxf(v, __shfl_xor_sync(0xffffffffu, v, o));
        if ((tid & 15) == 0)
            g_m2x[(cbase+c)*H_ + (j >> 4)] = v;
    }
}

__global__ __launch_bounds__(256)
void k_ex3(const float* __restrict__ w3, const float* __restrict__ b3, int phase) {
    __shared__ float w3sm[16*512];
    int nc = min(g_ncand8[phase], CAP);
    int tid = threadIdx.x;
    int c = blockIdx.x*8 + (tid >> 5);
    int lane = tid & 31;
    if (blockIdx.x*8 >= nc) return;
    for (int idx = tid; idx < 16*512; idx += 256) w3sm[idx] = w3[idx];
    __syncthreads();
    if (c >= nc) return;
    float acc[16];
    #pragma unroll
    for (int p = 0; p < 16; p++) acc[p] = 0.f;
    #pragma unroll
    for (int ki = 0; ki < 16; ki++) {
        int k = ki*32 + lane;
        float x = (ki < 8) ? g_m1x[c*H_ + k] : g_m2x[c*H_ + k - 256];
        #pragma unroll
        for (int p = 0; p < 16; p++) acc[p] += x * w3sm[p*512 + k];
    }
    #pragma unroll
    for (int p = 0; p < 16; p++)
        #pragma unroll
        for (int off = 16; off; off >>= 1)
            acc[p] += __shfl_down_sync(0xffffffffu, acc[p], off);
    if (lane == 0) {
        float s = -1e30f;
        #pragma unroll
        for (int p = 0; p < 16; p++) s = fmaxf(s, acc[p] + b3[p]);
        g_sexact[c] = s;
    }
}

__global__ void k_argmax2(const float* __restrict__ enc, float* __restrict__ out,
                          int outoff, int useEnd, int phase) {
    __shared__ float sv[512];
    __shared__ int   si[512];
    __shared__ int   sidx;
    int b = blockIdx.x, tid = threadIdx.x;
    int nc = min(g_ncand8[phase], CAP);
    float best = -1e30f; int bi = 1 << 30;
    for (int i = tid; i < nc; i += 512) {
        int bt = g_cands[i];
        if ((bt >> 9) == b) {
            float v = g_sexact[i]; int t = bt & 511;
            if (v > best || (v == best && t < bi)) { best = v; bi = t; }
        }
    }
    sv[tid] = best; si[tid] = bi;
    __syncthreads();
    for (int s = 256; s; s >>= 1) {
        if (tid < s) {
            float v2 = sv[tid+s]; int i2 = si[tid+s];
            if (v2 > sv[tid] || (v2 == sv[tid] && i2 < si[tid])) { sv[tid] = v2; si[tid] = i2; }
        }
        __syncthreads();
    }
    if (tid == 0) { sidx = si[0]; out[outoff + b] = (float)si[0]; }
    __syncthreads();
    int idx = sidx;
    float* sel = useEnd ? g_ence : g_encs;
    sel[b*C2H + tid] = enc[(size_t)b*C2H*T_ + (size_t)tid*T_ + idx];
}

__device__ __forceinline__ float sigf(float x) { return 1.f / (1.f + expf(-x)); }

// fused LSTM gates + cell + MLP, ILP-optimized (same 32-block shape as before)
__global__ void k_lstmfused(const float* __restrict__ bih, const float* __restrict__ bhh,
                            const float* __restrict__ bmlp) {
    __shared__ float xs[1024];
    __shared__ float hs[256];
    __shared__ float hp[256];
    __shared__ float gsm[1024];
    __shared__ float part[4][256];
    int b = blockIdx.x, j = threadIdx.x;  // 1024 threads
    xs[j] = (j < 512) ? g_encs[b*C2H + j] : g_ence[b*C2H + j - 512];
    if (j < 256) hs[j] = g_hx[b*H_ + j];
    __syncthreads();
    float a0 = 0.f, a1 = 0.f, a2 = 0.f, a3 = 0.f;
    #pragma unroll 4
    for (int k = 0; k < 1024; k += 4) {
        a0 = fmaf(xs[k],   g_WihT[(size_t)k*1024 + j],       a0);
        a1 = fmaf(xs[k+1], g_WihT[(size_t)(k+1)*1024 + j],   a1);
        a2 = fmaf(xs[k+2], g_WihT[(size_t)(k+2)*1024 + j],   a2);
        a3 = fmaf(xs[k+3], g_WihT[(size_t)(k+3)*1024 + j],   a3);
    }
    #pragma unroll 4
    for (int k = 0; k < 256; k += 4) {
        a0 = fmaf(hs[k],   g_WhhT[(size_t)k*1024 + j],       a0);
        a1 = fmaf(hs[k+1], g_WhhT[(size_t)(k+1)*1024 + j],   a1);
        a2 = fmaf(hs[k+2], g_WhhT[(size_t)(k+2)*1024 + j],   a2);
        a3 = fmaf(hs[k+3], g_WhhT[(size_t)(k+3)*1024 + j],   a3);
    }
    gsm[j] = bih[j] + bhh[j] + (a0 + a1) + (a2 + a3);
    __syncthreads();
    if (j < 256) {
        float i_ = gsm[j], f_ = gsm[256 + j], gg = gsm[512 + j], o_ = gsm[768 + j];
        float c = sigf(f_) * g_cx[b*H_ + j] + sigf(i_) * tanhf(gg);
        g_cx[b*H_ + j] = c;
        hp[j] = sigf(o_) * tanhf(c);
    }
    __syncthreads();
    {
        int h = j & 255, ks = j >> 8;
        float m = 0.f;
        int k0 = ks*64;
        #pragma unroll 8
        for (int k = k0; k < k0 + 64; k++)
            m = fmaf(hp[k], g_WmlpT[k*H_ + h], m);
        part[ks][h] = m;
    }
    __syncthreads();
    if (j < 256)
        g_hx[b*H_ + j] = bmlp[j] + (part[0][j] + part[1][j]) + (part[2][j] + part[3][j]);
}

// ---------------- launch ----------------
extern "C" void kernel_launch(void* const* d_in, const int* in_sizes, int n_in,
                              void* d_out, int out_size) {
    const float* enc  = (const float*)d_in[0];
    const int*   plen = (const int*)d_in[1];
    const float* WDs  = (const float*)d_in[2];
    const float* w1s  = (const float*)d_in[3];
    const float* b1s  = (const float*)d_in[4];
    const float* w2s  = (const float*)d_in[5];
    const float* b2s  = (const float*)d_in[6];
    const float* w3s  = (const float*)d_in[7];
    const float* b3s  = (const float*)d_in[8];
    const float* WDe  = (const float*)d_in[9];
    const float* w1e  = (const float*)d_in[10];
    const float* b1e  = (const float*)d_in[11];
    const float* w2e  = (const float*)d_in[12];
    const float* b2e  = (const float*)d_in[13];
    const float* w3e  = (const float*)d_in[14];
    const float* b3e  = (const float*)d_in[15];
    const float* Wih  = (const float*)d_in[16];
    const float* Whh  = (const float*)d_in[17];
    const float* bih  = (const float*)d_in[18];
    const float* bhh  = (const float*)d_in[19];
    const float* Wmlp = (const float*)d_in[20];
    const float* bmlp = (const float*)d_in[21];
    float* out = (float*)d_out;

    cudaFuncSetAttribute(gemm_cp<0>, cudaFuncAttributeMaxDynamicSharedMemorySize, GEMM_DSMEM);
    cudaFuncSetAttribute(gemm_cp<1>, cudaFuncAttributeMaxDynamicSharedMemorySize, GEMM_DSMEM);

    dim3 ggrid(HP/128, M_/128);   // (32, 128)

    k_init<<<B_, 512>>>(enc);                          // 0
    {
        dim3 g(16, 16, B_), blk(32, 8);
        k_tEt<<<g, blk>>>(enc);                        // 1
    }
    k_w1prep<<<2048, 256>>>(w1s, 0);                   // 2
    gemm_cp<0><<<ggrid, 256, GEMM_DSMEM>>>(b1s, 0);    // 3
    k_w1prep<<<2048, 256>>>(w1e, 1);                   // 4
    gemm_cp<0><<<ggrid, 256, GEMM_DSMEM>>>(b1e, 1);    // 5
    k_w2prep<<<1024, 256>>>(w2s, 0);
    k_w2prep<<<1024, 256>>>(w2e, 1);
    k_WDprep<<<512, 256>>>(WDs, 0);
    k_WDprep<<<512, 256>>>(WDe, 1);
    k_lstmprep<<<2048, 256>>>(Wih, Whh, Wmlp);

    const int ALPHA0 = 64;
    const int BETA0  = 64 + NITER*M_;
    dim3 exg(16, CAP/8);   // (16, 64)

    for (int it = 0; it < NITER; it++) {
        int phS = it*2, phE = it*2 + 1;
        // ---- start phase ----
        k_r<<<B_, 1024>>>(0);
        { dim3 gd(HP/256, B_); k_d<<<gd, 256>>>(0); }
        k_m1<<<B_*(T_/8), 256>>>(0);
        gemm_cp<1><<<ggrid, 256, GEMM_DSMEM>>>(b2s, 0);
        k_m3<<<M_/8, 256>>>(w3s, b3s, plen, out, ALPHA0 + it*M_);
        k_cand<<<B_, 512>>>(phS);
        k_ex1<<<exg, 256>>>(w1s, b1s, phS);
        k_ex2<<<exg, 256>>>(w2s, b2s, phS);
        k_ex3<<<CAP/8, 256>>>(w3s, b3s, phS);
        k_argmax2<<<B_, 512>>>(enc, out, 0, 0, phS);
        // ---- end phase ----
        k_r<<<B_, 1024>>>(1);
        { dim3 gd(HP/256, B_); k_d<<<gd, 256>>>(1); }
        k_m1<<<B_*(T_/8), 256>>>(1);
        gemm_cp<1><<<ggrid, 256, GEMM_DSMEM>>>(b2e, 1);
        k_m3<<<M_/8, 256>>>(w3e, b3e, plen, out, BETA0 + it*M_);
        k_cand<<<B_, 512>>>(phE);
        k_ex1<<<exg, 256>>>(w1e, b1e, phE);
        k_ex2<<<exg, 256>>>(w2e, b2e, phE);
        k_ex3<<<CAP/8, 256>>>(w3e, b3e, phE);
        k_argmax2<<<B_, 512>>>(enc, out, 32, 1, phE);
        // ---- LSTM + MLP (fused) ----
        k_lstmfused<<<B_, 1024>>>(bih, bhh, bmlp);
    }
}